// round 16
// baseline (speedup 1.0000x reference)
#include <cuda_runtime.h>
#include <cuda_fp16.h>
#include <cstdint>

#define B_ROWS 4096
#define IN_DIM 512
#define OUT_DIM 256
#define U_ROWS 8192

// ---------------- scratch ----------------
__device__ float   g_U [(size_t)U_ROWS * OUT_DIM];
__device__ __half  g_Uh[(size_t)U_ROWS * OUT_DIM];
__device__ __half  g_xh[(size_t)B_ROWS * IN_DIM];
__device__ __half  g_xl[(size_t)B_ROWS * IN_DIM];
__device__ __half  g_Wh[512 * IN_DIM];
__device__ float  g_sq[U_ROWS];
__device__ float  g_colsum[OUT_DIM];
__device__ float  g_lp0[65536];
__device__ float  g_lp1[65536];
__device__ float  g_sumsq;
__device__ double g_loss;
__device__ float  g_coef;
__device__ unsigned g_cnt1, g_cnt2;

// ---------------- helpers ----------------
__device__ __forceinline__ uint32_t smem_u32(const void* p) {
    uint32_t a;
    asm("{ .reg .u64 t; cvta.to.shared.u64 t, %1; cvt.u32.u64 %0, t; }" : "=r"(a) : "l"(p));
    return a;
}
__device__ __forceinline__ void ldsm4(uint32_t (&r)[4], uint32_t a) {
    asm volatile("ldmatrix.sync.aligned.m8n8.x4.shared.b16 {%0,%1,%2,%3}, [%4];"
                 : "=r"(r[0]), "=r"(r[1]), "=r"(r[2]), "=r"(r[3]) : "r"(a));
}
__device__ __forceinline__ void mma_f16(float* c, const uint32_t* a, uint32_t b0, uint32_t b1) {
    asm volatile("mma.sync.aligned.m16n8k16.row.col.f32.f16.f16.f32 "
                 "{%0,%1,%2,%3},{%4,%5,%6,%7},{%8,%9},{%0,%1,%2,%3};"
                 : "+f"(c[0]), "+f"(c[1]), "+f"(c[2]), "+f"(c[3])
                 : "r"(a[0]), "r"(a[1]), "r"(a[2]), "r"(a[3]), "r"(b0), "r"(b1));
}
__device__ __forceinline__ void cp16(uint32_t d, const void* s) {
    asm volatile("cp.async.cg.shared.global [%0], [%1], 16;" :: "r"(d), "l"(s));
}
#define CP_COMMIT() asm volatile("cp.async.commit_group;" ::: "memory")
#define CP_WAIT(n)  asm volatile("cp.async.wait_group %0;" :: "n"(n) : "memory")

// k_outs: pitch 80 B (32 data cols fp16), 3 arrays of 128 rows, QUAD buffered
#define ROWB   80
#define ARR    10240
#define SETSZ3  30720
#define DYNSZ3Q 122880          // 4 buffer sets
// k_pair: pitch 144 B (64 data cols fp16), 2 arrays, double buffered
#define ROWB2   144
#define ARR2    18432
#define SETSZ2  36864
#define DYNSZ2  73728

// ---------------- fp16 3-array pipeline (k_outs): dot = Ah*B + Al*B ----------------
template <int STRIDE>
__device__ __forceinline__ void load_chunk3(uint32_t sbase,
    const __half* Ah, const __half* Al, const __half* B, int k0, int tid)
{
    const int row0 = tid >> 2;
    const int c    = (tid & 3) * 8;
#pragma unroll
    for (int pass = 0; pass < 2; pass++) {
        const int row = row0 + pass * 64;
        const size_t go = (size_t)row * STRIDE + k0 + c;
        const uint32_t so = (uint32_t)(row * ROWB + c * 2);
        cp16(sbase + 0 * ARR + so, Ah + go);
        cp16(sbase + 1 * ARR + so, Al + go);
        cp16(sbase + 2 * ARR + so, B + go);
    }
}

__device__ __forceinline__ void compute_chunk3(uint32_t sbase, int wm, int wn, int lane,
                                               float (&acc)[2][8][4])
{
    const uint32_t lrow  = (uint32_t)(lane & 15);
    const uint32_t khalf = (uint32_t)((lane >> 4) * 16);
#pragma unroll
    for (int ks = 0; ks < 2; ks++) {
        const uint32_t kb = (uint32_t)(ks * 32) + khalf;
        uint32_t ah[2][4], al[2][4], bh[4][4];
#pragma unroll
        for (int mt = 0; mt < 2; mt++) {
            uint32_t r = (uint32_t)(wm * 32 + mt * 16) + lrow;
            ldsm4(ah[mt], sbase + 0 * ARR + r * ROWB + kb);
            ldsm4(al[mt], sbase + 1 * ARR + r * ROWB + kb);
        }
#pragma unroll
        for (int nt = 0; nt < 4; nt++) {
            uint32_t r = (uint32_t)(wn * 64 + nt * 16) + lrow;
            ldsm4(bh[nt], sbase + 2 * ARR + r * ROWB + kb);
        }
#pragma unroll
        for (int mt = 0; mt < 2; mt++)
#pragma unroll
            for (int nt = 0; nt < 4; nt++) {
                mma_f16(acc[mt][nt * 2 + 0], ah[mt], bh[nt][0], bh[nt][2]);
                mma_f16(acc[mt][nt * 2 + 1], ah[mt], bh[nt][1], bh[nt][3]);
            }
#pragma unroll
        for (int mt = 0; mt < 2; mt++)
#pragma unroll
            for (int nt = 0; nt < 4; nt++) {
                mma_f16(acc[mt][nt * 2 + 0], al[mt], bh[nt][0], bh[nt][2]);
                mma_f16(acc[mt][nt * 2 + 1], al[mt], bh[nt][1], bh[nt][3]);
            }
    }
}

// ---------------- fp16 2-array pipeline (k_pair), 64-col chunks ----------------
__device__ __forceinline__ void load_chunk2(uint32_t sbase,
    const __half* A, const __half* B, int k0, int tid)
{
    const int row0 = tid >> 3;
    const int c    = (tid & 7) * 8;
#pragma unroll
    for (int pass = 0; pass < 4; pass++) {
        const int row = row0 + pass * 32;
        const size_t go = (size_t)row * OUT_DIM + k0 + c;
        const uint32_t so = (uint32_t)(row * ROWB2 + c * 2);
        cp16(sbase + 0 * ARR2 + so, A + go);
        cp16(sbase + 1 * ARR2 + so, B + go);
    }
}

__device__ __forceinline__ void compute_chunk2(uint32_t sbase, int wm, int wn, int lane,
                                               float (&acc)[2][8][4])
{
    const uint32_t lrow  = (uint32_t)(lane & 15);
    const uint32_t khalf = (uint32_t)((lane >> 4) * 16);
#pragma unroll
    for (int ks = 0; ks < 4; ks++) {
        const uint32_t kb = (uint32_t)(ks * 32) + khalf;
        uint32_t ah[2][4], bh[4][4];
#pragma unroll
        for (int mt = 0; mt < 2; mt++) {
            uint32_t r = (uint32_t)(wm * 32 + mt * 16) + lrow;
            ldsm4(ah[mt], sbase + 0 * ARR2 + r * ROWB2 + kb);
        }
#pragma unroll
        for (int nt = 0; nt < 4; nt++) {
            uint32_t r = (uint32_t)(wn * 64 + nt * 16) + lrow;
            ldsm4(bh[nt], sbase + 1 * ARR2 + r * ROWB2 + kb);
        }
#pragma unroll
        for (int mt = 0; mt < 2; mt++)
#pragma unroll
            for (int nt = 0; nt < 4; nt++) {
                mma_f16(acc[mt][nt * 2 + 0], ah[mt], bh[nt][0], bh[nt][2]);
                mma_f16(acc[mt][nt * 2 + 1], ah[mt], bh[nt][1], bh[nt][3]);
            }
    }
}

__device__ __forceinline__ float kernF(float d, float coef) {
    float u;
    asm("ex2.approx.f32 %0, %1;" : "=f"(u) : "f"(coef * d));
    float u2 = u * u, u4 = u2 * u2, u8 = u4 * u4, u16 = u8 * u8;
    return (u + u2) + (u4 + u8) + u16;
}

// ---------------- kernel 1: prep (splits + warp logit partials + zeroing) --------
__global__ void k_prep(const float* __restrict__ x, const float* __restrict__ W,
                       const float* __restrict__ Waux) {
    const int b = blockIdx.x, t = threadIdx.x;
    if (b < 8192) {
        int i = b * 256 + t;
        int col = (b & 1) * 256 + t;
        float v = x[i];
        __half h = __float2half_rn(v);
        g_xh[i] = h;
        g_xl[i] = __float2half_rn(v - __half2float(h));
        float p0 = v * Waux[col];
        float p1 = v * Waux[IN_DIM + col];
#pragma unroll
        for (int off = 16; off; off >>= 1) {
            p0 += __shfl_down_sync(0xffffffffu, p0, off);
            p1 += __shfl_down_sync(0xffffffffu, p1, off);
        }
        if ((t & 31) == 0) {
            int w = t >> 5;
            g_lp0[b * 8 + w] = p0;
            g_lp1[b * 8 + w] = p1;
        }
    } else if (b < 9216) {
        int i = (b - 8192) * 256 + t;
        g_Wh[i] = __float2half_rn(W[i]);
    } else {
        g_colsum[t] = 0.f;
        if (t == 0) { g_sumsq = 0.f; g_loss = 0.0; g_cnt1 = 0u; g_cnt2 = 0u; }
    }
}

// ---------------- kernel 2: outs GEMM (fp16 2-combo, 128x128, quad-buffered) -----
__global__ __launch_bounds__(256, 1) void k_outs_tc(const float* __restrict__ bias) {
    extern __shared__ char dyn[];
    uint32_t sdyn = smem_u32(dyn);
    const int tid = threadIdx.x, lane = tid & 31, wid = tid >> 5;
    const int wm = wid & 3, wn = wid >> 2;
    const int bn = blockIdx.x, bm = blockIdx.y;

    float acc[2][8][4];
#pragma unroll
    for (int a = 0; a < 2; a++)
#pragma unroll
        for (int b = 0; b < 8; b++)
#pragma unroll
            for (int r = 0; r < 4; r++) acc[a][b][r] = 0.f;

    const __half* Ah = g_xh + (size_t)bm * 128 * IN_DIM;
    const __half* Al = g_xl + (size_t)bm * 128 * IN_DIM;
    const __half* B  = g_Wh + (size_t)bn * 128 * IN_DIM;

    // preload 4 chunks
#pragma unroll
    for (int q = 0; q < 4; q++) {
        load_chunk3<IN_DIM>(sdyn + q * SETSZ3, Ah, Al, B, q * 32, tid);
        CP_COMMIT();
    }
#pragma unroll
    for (int p = 0; p < 16; p++) {
        CP_WAIT(3);                 // chunk p resident (<=3 groups pending)
        __syncthreads();
        compute_chunk3(sdyn + (p & 3) * SETSZ3, wm, wn, lane, acc);
        __syncthreads();
        if (p + 4 < 16) {
            load_chunk3<IN_DIM>(sdyn + (p & 3) * SETSZ3, Ah, Al, B, (p + 4) * 32, tid);
            CP_COMMIT();
        }
    }

#pragma unroll
    for (int mt = 0; mt < 2; mt++) {
        const int rb = bm * 128 + wm * 32 + mt * 16 + (lane >> 2);
#pragma unroll
        for (int n8 = 0; n8 < 8; n8++) {
            const int nb = bn * 128 + wn * 64 + n8 * 8 + (lane & 3) * 2;
            const float2 bs = *(const float2*)&bias[nb];
            const int l = nb >> 8, o = nb & 255;
#pragma unroll
            for (int rp = 0; rp < 2; rp++) {
                const int rr = rb + rp * 8;
                float v0 = acc[mt][n8][rp * 2 + 0] + bs.x;
                float v1 = acc[mt][n8][rp * 2 + 1] + bs.y;
                size_t gi = ((size_t)(l * B_ROWS + rr)) * OUT_DIM + o;
                *(float2*)&g_U[gi] = make_float2(v0, v1);
                __half2 hp; hp.x = __float2half_rn(v0); hp.y = __float2half_rn(v1);
                *(__half2*)&g_Uh[gi] = hp;
            }
        }
    }
}

// ---------------- kernel 3: rowstats + bandwidth finalize (256 blocks) -----------
__global__ void k_rowstats() {
    __shared__ float red[256];
    __shared__ int lastFlag;
    const int tid = threadIdx.x;
    const int r0  = blockIdx.x * 32;
    float cs = 0.f;
    for (int r = 0; r < 32; r++) cs += g_U[(size_t)(r0 + r) * OUT_DIM + tid];
    atomicAdd(&g_colsum[tid], cs);
    int w = tid >> 5, lane = tid & 31;
    float warpsq = 0.f;
    for (int rr = w; rr < 32; rr += 8) {
        const float* row = g_U + (size_t)(r0 + rr) * OUT_DIM;
        float s = 0.f;
#pragma unroll
        for (int c = lane; c < OUT_DIM; c += 32) { float v = row[c]; s = fmaf(v, v, s); }
#pragma unroll
        for (int off = 16; off; off >>= 1) s += __shfl_down_sync(0xffffffffu, s, off);
        if (lane == 0) { g_sq[r0 + rr] = s; warpsq += s; }
    }
    if (lane == 0) atomicAdd(&g_sumsq, warpsq);

    __threadfence();
    if (tid == 0) lastFlag = (atomicAdd(&g_cnt1, 1u) == 255u) ? 1 : 0;
    __syncthreads();
    if (lastFlag) {
        float c = g_colsum[tid];
        red[tid] = c * c;
        __syncthreads();
        for (int s = 128; s; s >>= 1) { if (tid < s) red[tid] += red[tid + s]; __syncthreads(); }
        if (tid == 0) {
            double s2 = (double)red[0];
            double sumsq = (double)g_sumsq;
            double n = (double)U_ROWS;
            double bw = (2.0 * n * sumsq - 2.0 * s2) / (n * (n - 1.0));
            g_coef = (float)(-1.4426950408889634 / (4.0 * bw));
        }
    }
}

// ---------------- kernel 4: gates + combine (4 rows/block, float4) ---------------
__global__ void k_gates(const float* __restrict__ baux, float* __restrict__ out) {
    __shared__ float sg[8];
    const int tid = threadIdx.x, lane = tid & 31, w = tid >> 5;
    const int rloc = w >> 1;
    const int b = blockIdx.x * 4 + rloc;
    if ((w & 1) == 0) {
        float p = (lane < 16) ? g_lp0[b * 16 + lane] : g_lp1[b * 16 + (lane - 16)];
#pragma unroll
        for (int off = 8; off; off >>= 1) p += __shfl_down_sync(0xffffffffu, p, off);
        if (lane == 0)  sg[rloc * 2 + 0] = p;
        if (lane == 16) sg[rloc * 2 + 1] = p;
    }
    __syncthreads();
    float l0 = sg[rloc * 2 + 0] + baux[0];
    float l1 = sg[rloc * 2 + 1] + baux[1];
    float gg0 = 1.f / (1.f + expf(l1 - l0));
    float gg1 = 1.f - gg0;
    const int c = (w & 1) * 128 + lane * 4;
    float4 u0 = *(const float4*)&g_U[(size_t)b * OUT_DIM + c];
    float4 u1 = *(const float4*)&g_U[(size_t)(B_ROWS + b) * OUT_DIM + c];
    float4 o;
    o.x = gg0 * u0.x + gg1 * u1.x;
    o.y = gg0 * u0.y + gg1 * u1.y;
    o.z = gg0 * u0.z + gg1 * u1.z;
    o.w = gg0 * u0.w + gg1 * u1.w;
    *(float4*)&out[(size_t)b * OUT_DIM + c] = o;
}

// ---------------- kernel 5: pairwise Gram + kernel-sum + final scalar ------------
__global__ __launch_bounds__(256, 2) void k_pair_tc(float* __restrict__ out, int idx) {
    extern __shared__ char dyn[];
    __shared__ float sSqI[128], sSqJ[128], sRed[8];
    uint32_t sdyn = smem_u32(dyn);
    const int tid = threadIdx.x, lane = tid & 31, wid = tid >> 5;
    const int wm = wid & 3, wn = wid >> 2;

    int t = blockIdx.x;
    int s = 2079 - t;
    int a = (int)((sqrtf(8.f * (float)s + 1.f) - 1.f) * 0.5f);
    while ((a + 1) * (a + 2) / 2 <= s) a++;
    while (a * (a + 1) / 2 > s) a--;
    const int bi = 63 - a;
    const int bj = 63 - (s - a * (a + 1) / 2);
    const int i0 = bi * 128, j0 = bj * 128;

    if (tid < 128) { sSqI[tid] = g_sq[i0 + tid]; sSqJ[tid] = g_sq[j0 + tid]; }

    float acc[2][8][4];
#pragma unroll
    for (int aa = 0; aa < 2; aa++)
#pragma unroll
        for (int b = 0; b < 8; b++)
#pragma unroll
            for (int r = 0; r < 4; r++) acc[aa][b][r] = 0.f;

    const __half* A = g_Uh + (size_t)i0 * OUT_DIM;
    const __half* B = g_Uh + (size_t)j0 * OUT_DIM;

    load_chunk2(sdyn, A, B, 0, tid);
    CP_COMMIT();
#pragma unroll
    for (int p = 0; p < 4; p++) {
        if (p + 1 < 4) {
            load_chunk2(sdyn + ((p + 1) & 1) * SETSZ2, A, B, (p + 1) * 64, tid);
            CP_COMMIT();
            CP_WAIT(1);
        } else {
            CP_WAIT(0);
        }
        __syncthreads();
        compute_chunk2(sdyn + (p & 1) * SETSZ2, wm, wn, lane, acc);
        __syncthreads();
    }

    const float coef = g_coef;
    const float sgn = ((bi < 32) == (bj < 32)) ? 1.f : -1.f;
    float local = 0.f;
    float blockScale;

    if (bi != bj) {
        const int ibase = wm * 32 + (lane >> 2);
        const int jb0   = wn * 64 + (lane & 3) * 2;
#pragma unroll
        for (int mt = 0; mt < 2; mt++) {
            const float si0 = sSqI[ibase + mt * 16];
            const float si1 = sSqI[ibase + mt * 16 + 8];
#pragma unroll
            for (int n8 = 0; n8 < 8; n8++) {
                const float2 sj = *(const float2*)&sSqJ[jb0 + n8 * 8];
                const float* q = acc[mt][n8];
                local += kernF(si0 + sj.x - 2.f * q[0], coef);
                local += kernF(si0 + sj.y - 2.f * q[1], coef);
                local += kernF(si1 + sj.x - 2.f * q[2], coef);
                local += kernF(si1 + sj.y - 2.f * q[3], coef);
            }
        }
        blockScale = 2.f * sgn;
    } else {
#pragma unroll
        for (int mt = 0; mt < 2; mt++) {
            const int ibase = wm * 32 + mt * 16 + (lane >> 2);
#pragma unroll
            for (int n8 = 0; n8 < 8; n8++) {
                const int jbase = wn * 64 + n8 * 8 + (lane & 3) * 2;
#pragma unroll
                for (int r = 0; r < 4; r++) {
                    const int i = ibase + (r >> 1) * 8;
                    const int j = jbase + (r & 1);
                    float w = (j > i) ? 2.f : (j == i ? 1.f : 0.f);
                    local += w * kernF(sSqI[i] + sSqJ[j] - 2.f * acc[mt][n8][r], coef);
                }
            }
        }
        blockScale = sgn;
    }

#pragma unroll
    for (int off = 16; off; off >>= 1) local += __shfl_down_sync(0xffffffffu, local, off);
    if (lane == 0) sRed[wid] = local;
    __syncthreads();
    if (tid == 0) {
        float tot = 0.f;
#pragma unroll
        for (int ww = 0; ww < 8; ww++) tot += sRed[ww];
        atomicAdd(&g_loss, (double)tot * (double)blockScale);
        __threadfence();
        if (atomicAdd(&g_cnt2, 1u) == 2079u)
            out[idx] = (float)(-g_loss / ((double)B_ROWS * (double)B_ROWS));
    }
}

// ---------------- launch ----------------
extern "C" void kernel_launch(void* const* d_in, const int* in_sizes, int n_in,
                              void* d_out, int out_size) {
    const float* x    = (const float*)d_in[0];
    const float* Waux = (const float*)d_in[1];
    const float* baux = (const float*)d_in[2];
    const float* W    = (const float*)d_in[3];
    const float* bias = (const float*)d_in[4];
    float* out = (float*)d_out;

    cudaFuncSetAttribute(k_outs_tc, cudaFuncAttributeMaxDynamicSharedMemorySize, DYNSZ3Q);
    cudaFuncSetAttribute(k_pair_tc, cudaFuncAttributeMaxDynamicSharedMemorySize, DYNSZ2);

    k_prep<<<9217, 256>>>(x, W, Waux);
    k_outs_tc<<<dim3(4, 32), 256, DYNSZ3Q>>>(bias);
    k_rowstats<<<256, 256>>>();
    k_gates<<<1024, 256>>>(baux, out);
    k_pair_tc<<<2080, 256, DYNSZ2>>>(out, out_size - 1);
}

// round 17
// speedup vs baseline: 1.0407x; 1.0407x over previous
#include <cuda_runtime.h>
#include <cuda_fp16.h>
#include <cstdint>

#define B_ROWS 4096
#define IN_DIM 512
#define OUT_DIM 256
#define U_ROWS 8192

// ---------------- scratch ----------------
__device__ float   g_U [(size_t)U_ROWS * OUT_DIM];
__device__ __half  g_Uh[(size_t)U_ROWS * OUT_DIM];
__device__ __half  g_xh[(size_t)B_ROWS * IN_DIM];
__device__ __half  g_xl[(size_t)B_ROWS * IN_DIM];
__device__ __half  g_Wh[512 * IN_DIM];
__device__ float  g_sq[U_ROWS];
__device__ float  g_colsum[OUT_DIM];
__device__ float  g_lp0[16384];   // 4 per row
__device__ float  g_lp1[16384];
__device__ float  g_sumsq;
__device__ double g_loss;
__device__ float  g_coef;
__device__ unsigned g_cnt1, g_cnt2;

// ---------------- helpers ----------------
__device__ __forceinline__ uint32_t smem_u32(const void* p) {
    uint32_t a;
    asm("{ .reg .u64 t; cvta.to.shared.u64 t, %1; cvt.u32.u64 %0, t; }" : "=r"(a) : "l"(p));
    return a;
}
__device__ __forceinline__ void ldsm4(uint32_t (&r)[4], uint32_t a) {
    asm volatile("ldmatrix.sync.aligned.m8n8.x4.shared.b16 {%0,%1,%2,%3}, [%4];"
                 : "=r"(r[0]), "=r"(r[1]), "=r"(r[2]), "=r"(r[3]) : "r"(a));
}
__device__ __forceinline__ void mma_f16(float* c, const uint32_t* a, uint32_t b0, uint32_t b1) {
    asm volatile("mma.sync.aligned.m16n8k16.row.col.f32.f16.f16.f32 "
                 "{%0,%1,%2,%3},{%4,%5,%6,%7},{%8,%9},{%0,%1,%2,%3};"
                 : "+f"(c[0]), "+f"(c[1]), "+f"(c[2]), "+f"(c[3])
                 : "r"(a[0]), "r"(a[1]), "r"(a[2]), "r"(a[3]), "r"(b0), "r"(b1));
}
__device__ __forceinline__ void cp16(uint32_t d, const void* s) {
    asm volatile("cp.async.cg.shared.global [%0], [%1], 16;" :: "r"(d), "l"(s));
}
#define CP_COMMIT() asm volatile("cp.async.commit_group;" ::: "memory")
#define CP_WAIT(n)  asm volatile("cp.async.wait_group %0;" :: "n"(n) : "memory")

// pack 2 floats -> half2 as uint32
__device__ __forceinline__ uint32_t packh2(float a, float b) {
    __half2 h; h.x = __float2half_rn(a); h.y = __float2half_rn(b);
    return *(uint32_t*)&h;
}

// k_outs: pitch 80 B (32 data cols fp16), 3 arrays of 128 rows, double buffered
#define ROWB   80
#define ARR    10240
#define SETSZ3  30720
#define DYNSZ3  61440
// k_pair: pitch 144 B (64 data cols fp16), 2 arrays, double buffered
#define ROWB2   144
#define ARR2    18432
#define SETSZ2  36864
#define DYNSZ2  73728

// ---------------- fp16 3-array pipeline (k_outs): dot = Ah*B + Al*B ----------------
template <int STRIDE>
__device__ __forceinline__ void load_chunk3(uint32_t sbase,
    const __half* Ah, const __half* Al, const __half* B, int k0, int tid)
{
    const int row0 = tid >> 2;
    const int c    = (tid & 3) * 8;
#pragma unroll
    for (int pass = 0; pass < 2; pass++) {
        const int row = row0 + pass * 64;
        const size_t go = (size_t)row * STRIDE + k0 + c;
        const uint32_t so = (uint32_t)(row * ROWB + c * 2);
        cp16(sbase + 0 * ARR + so, Ah + go);
        cp16(sbase + 1 * ARR + so, Al + go);
        cp16(sbase + 2 * ARR + so, B + go);
    }
}

__device__ __forceinline__ void compute_chunk3(uint32_t sbase, int wm, int wn, int lane,
                                               float (&acc)[2][8][4])
{
    const uint32_t lrow  = (uint32_t)(lane & 15);
    const uint32_t khalf = (uint32_t)((lane >> 4) * 16);
#pragma unroll
    for (int ks = 0; ks < 2; ks++) {
        const uint32_t kb = (uint32_t)(ks * 32) + khalf;
        uint32_t ah[2][4], al[2][4], bh[4][4];
#pragma unroll
        for (int mt = 0; mt < 2; mt++) {
            uint32_t r = (uint32_t)(wm * 32 + mt * 16) + lrow;
            ldsm4(ah[mt], sbase + 0 * ARR + r * ROWB + kb);
            ldsm4(al[mt], sbase + 1 * ARR + r * ROWB + kb);
        }
#pragma unroll
        for (int nt = 0; nt < 4; nt++) {
            uint32_t r = (uint32_t)(wn * 64 + nt * 16) + lrow;
            ldsm4(bh[nt], sbase + 2 * ARR + r * ROWB + kb);
        }
#pragma unroll
        for (int mt = 0; mt < 2; mt++)
#pragma unroll
            for (int nt = 0; nt < 4; nt++) {
                mma_f16(acc[mt][nt * 2 + 0], ah[mt], bh[nt][0], bh[nt][2]);
                mma_f16(acc[mt][nt * 2 + 1], ah[mt], bh[nt][1], bh[nt][3]);
            }
#pragma unroll
        for (int mt = 0; mt < 2; mt++)
#pragma unroll
            for (int nt = 0; nt < 4; nt++) {
                mma_f16(acc[mt][nt * 2 + 0], al[mt], bh[nt][0], bh[nt][2]);
                mma_f16(acc[mt][nt * 2 + 1], al[mt], bh[nt][1], bh[nt][3]);
            }
    }
}

// ---------------- fp16 2-array pipeline (k_pair), 64-col chunks ----------------
__device__ __forceinline__ void load_chunk2(uint32_t sbase,
    const __half* A, const __half* B, int k0, int tid)
{
    const int row0 = tid >> 3;
    const int c    = (tid & 7) * 8;
#pragma unroll
    for (int pass = 0; pass < 4; pass++) {
        const int row = row0 + pass * 32;
        const size_t go = (size_t)row * OUT_DIM + k0 + c;
        const uint32_t so = (uint32_t)(row * ROWB2 + c * 2);
        cp16(sbase + 0 * ARR2 + so, A + go);
        cp16(sbase + 1 * ARR2 + so, B + go);
    }
}

__device__ __forceinline__ void compute_chunk2(uint32_t sbase, int wm, int wn, int lane,
                                               float (&acc)[2][8][4])
{
    const uint32_t lrow  = (uint32_t)(lane & 15);
    const uint32_t khalf = (uint32_t)((lane >> 4) * 16);
#pragma unroll
    for (int ks = 0; ks < 4; ks++) {
        const uint32_t kb = (uint32_t)(ks * 32) + khalf;
        uint32_t ah[2][4], bh[4][4];
#pragma unroll
        for (int mt = 0; mt < 2; mt++) {
            uint32_t r = (uint32_t)(wm * 32 + mt * 16) + lrow;
            ldsm4(ah[mt], sbase + 0 * ARR2 + r * ROWB2 + kb);
        }
#pragma unroll
        for (int nt = 0; nt < 4; nt++) {
            uint32_t r = (uint32_t)(wn * 64 + nt * 16) + lrow;
            ldsm4(bh[nt], sbase + 1 * ARR2 + r * ROWB2 + kb);
        }
#pragma unroll
        for (int mt = 0; mt < 2; mt++)
#pragma unroll
            for (int nt = 0; nt < 4; nt++) {
                mma_f16(acc[mt][nt * 2 + 0], ah[mt], bh[nt][0], bh[nt][2]);
                mma_f16(acc[mt][nt * 2 + 1], ah[mt], bh[nt][1], bh[nt][3]);
            }
    }
}

__device__ __forceinline__ float kernF(float d, float coef) {
    float u;
    asm("ex2.approx.f32 %0, %1;" : "=f"(u) : "f"(coef * d));
    float u2 = u * u, u4 = u2 * u2, u8 = u4 * u4, u16 = u8 * u8;
    return (u + u2) + (u4 + u8) + u16;
}

// ---------------- kernel 1: prep (vectorized splits + logit partials + zero) -----
// blocks [0, 2048)    : x rows 2b, 2b+1 (float4 per thread; 4 logit partials/row)
// blocks [2048, 2304) : W split (float4 per thread)
// block  2304         : zero accumulators
__global__ void k_prep(const float* __restrict__ x, const float* __restrict__ W,
                       const float* __restrict__ Waux) {
    const int b = blockIdx.x, t = threadIdx.x;
    if (b < 2048) {
        const int rloc = t >> 7;               // 0..1
        const int tt   = t & 127;
        const int row  = b * 2 + rloc;
        const int col  = tt * 4;
        float4 v = *(const float4*)&x[(size_t)row * IN_DIM + col];
        // split to fp16 hi/lo
        uint32_t h01 = packh2(v.x, v.y), h23 = packh2(v.z, v.w);
        __half2 h01h = *(__half2*)&h01, h23h = *(__half2*)&h23;
        uint32_t l01 = packh2(v.x - __half2float(h01h.x), v.y - __half2float(h01h.y));
        uint32_t l23 = packh2(v.z - __half2float(h23h.x), v.w - __half2float(h23h.y));
        *(uint2*)&g_xh[(size_t)row * IN_DIM + col] = make_uint2(h01, h23);
        *(uint2*)&g_xl[(size_t)row * IN_DIM + col] = make_uint2(l01, l23);
        // logit partials (one per 128-col warp segment)
        float4 wa0 = *(const float4*)&Waux[col];
        float4 wa1 = *(const float4*)&Waux[IN_DIM + col];
        float p0 = v.x * wa0.x + v.y * wa0.y + v.z * wa0.z + v.w * wa0.w;
        float p1 = v.x * wa1.x + v.y * wa1.y + v.z * wa1.z + v.w * wa1.w;
#pragma unroll
        for (int off = 16; off; off >>= 1) {
            p0 += __shfl_down_sync(0xffffffffu, p0, off);
            p1 += __shfl_down_sync(0xffffffffu, p1, off);
        }
        if ((t & 31) == 0) {
            int w4 = (t >> 5) & 3;
            g_lp0[row * 4 + w4] = p0;
            g_lp1[row * 4 + w4] = p1;
        }
    } else if (b < 2304) {
        int i = ((b - 2048) * 256 + t) * 4;
        float4 v = *(const float4*)&W[i];
        *(uint2*)&g_Wh[i] = make_uint2(packh2(v.x, v.y), packh2(v.z, v.w));
    } else {
        g_colsum[t] = 0.f;
        if (t == 0) { g_sumsq = 0.f; g_loss = 0.0; g_cnt1 = 0u; g_cnt2 = 0u; }
    }
}

// ---------------- kernel 2: outs GEMM (fp16 2-combo, 128x128, double-buffered) ---
__global__ __launch_bounds__(256, 2) void k_outs_tc(const float* __restrict__ bias) {
    extern __shared__ char dyn[];
    uint32_t sdyn = smem_u32(dyn);
    const int tid = threadIdx.x, lane = tid & 31, wid = tid >> 5;
    const int wm = wid & 3, wn = wid >> 2;
    const int bn = blockIdx.x, bm = blockIdx.y;

    float acc[2][8][4];
#pragma unroll
    for (int a = 0; a < 2; a++)
#pragma unroll
        for (int b = 0; b < 8; b++)
#pragma unroll
            for (int r = 0; r < 4; r++) acc[a][b][r] = 0.f;

    const __half* Ah = g_xh + (size_t)bm * 128 * IN_DIM;
    const __half* Al = g_xl + (size_t)bm * 128 * IN_DIM;
    const __half* B  = g_Wh + (size_t)bn * 128 * IN_DIM;

    load_chunk3<IN_DIM>(sdyn, Ah, Al, B, 0, tid);
    CP_COMMIT();
#pragma unroll
    for (int p = 0; p < 16; p++) {
        if (p + 1 < 16) {
            load_chunk3<IN_DIM>(sdyn + ((p + 1) & 1) * SETSZ3, Ah, Al, B, (p + 1) * 32, tid);
            CP_COMMIT();
            CP_WAIT(1);
        } else {
            CP_WAIT(0);
        }
        __syncthreads();
        compute_chunk3(sdyn + (p & 1) * SETSZ3, wm, wn, lane, acc);
        __syncthreads();
    }

#pragma unroll
    for (int mt = 0; mt < 2; mt++) {
        const int rb = bm * 128 + wm * 32 + mt * 16 + (lane >> 2);
#pragma unroll
        for (int n8 = 0; n8 < 8; n8++) {
            const int nb = bn * 128 + wn * 64 + n8 * 8 + (lane & 3) * 2;
            const float2 bs = *(const float2*)&bias[nb];
            const int l = nb >> 8, o = nb & 255;
#pragma unroll
            for (int rp = 0; rp < 2; rp++) {
                const int rr = rb + rp * 8;
                float v0 = acc[mt][n8][rp * 2 + 0] + bs.x;
                float v1 = acc[mt][n8][rp * 2 + 1] + bs.y;
                size_t gi = ((size_t)(l * B_ROWS + rr)) * OUT_DIM + o;
                *(float2*)&g_U[gi] = make_float2(v0, v1);
                __half2 hp; hp.x = __float2half_rn(v0); hp.y = __float2half_rn(v1);
                *(__half2*)&g_Uh[gi] = hp;
            }
        }
    }
}

// ---------------- kernel 3: rowstats + bandwidth finalize (256 blocks) -----------
__global__ void k_rowstats() {
    __shared__ float red[256];
    __shared__ int lastFlag;
    const int tid = threadIdx.x;
    const int r0  = blockIdx.x * 32;
    float cs = 0.f;
    for (int r = 0; r < 32; r++) cs += g_U[(size_t)(r0 + r) * OUT_DIM + tid];
    atomicAdd(&g_colsum[tid], cs);
    int w = tid >> 5, lane = tid & 31;
    float warpsq = 0.f;
    for (int rr = w; rr < 32; rr += 8) {
        const float* row = g_U + (size_t)(r0 + rr) * OUT_DIM;
        float s = 0.f;
#pragma unroll
        for (int c = lane; c < OUT_DIM; c += 32) { float v = row[c]; s = fmaf(v, v, s); }
#pragma unroll
        for (int off = 16; off; off >>= 1) s += __shfl_down_sync(0xffffffffu, s, off);
        if (lane == 0) { g_sq[r0 + rr] = s; warpsq += s; }
    }
    if (lane == 0) atomicAdd(&g_sumsq, warpsq);

    __threadfence();
    if (tid == 0) lastFlag = (atomicAdd(&g_cnt1, 1u) == 255u) ? 1 : 0;
    __syncthreads();
    if (lastFlag) {
        float c = g_colsum[tid];
        red[tid] = c * c;
        __syncthreads();
        for (int s = 128; s; s >>= 1) { if (tid < s) red[tid] += red[tid + s]; __syncthreads(); }
        if (tid == 0) {
            double s2 = (double)red[0];
            double sumsq = (double)g_sumsq;
            double n = (double)U_ROWS;
            double bw = (2.0 * n * sumsq - 2.0 * s2) / (n * (n - 1.0));
            g_coef = (float)(-1.4426950408889634 / (4.0 * bw));
        }
    }
}

// ---------------- kernel 4: gates + combine (4 rows/block, float4) ---------------
__global__ void k_gates(const float* __restrict__ baux, float* __restrict__ out) {
    __shared__ float sg[8];
    const int tid = threadIdx.x, lane = tid & 31, w = tid >> 5;
    const int rloc = w >> 1;
    const int b = blockIdx.x * 4 + rloc;
    if ((w & 1) == 0) {
        // 4 partials per logit: lanes 0-3 -> l0, lanes 16-19 -> l1
        float p = 0.f;
        if (lane < 4)                   p = g_lp0[b * 4 + lane];
        else if (lane >= 16 && lane < 20) p = g_lp1[b * 4 + (lane - 16)];
#pragma unroll
        for (int off = 2; off; off >>= 1) p += __shfl_down_sync(0xffffffffu, p, off);
        if (lane == 0)  sg[rloc * 2 + 0] = p;
        if (lane == 16) sg[rloc * 2 + 1] = p;
    }
    __syncthreads();
    float l0 = sg[rloc * 2 + 0] + baux[0];
    float l1 = sg[rloc * 2 + 1] + baux[1];
    float gg0 = 1.f / (1.f + expf(l1 - l0));
    float gg1 = 1.f - gg0;
    const int c = (w & 1) * 128 + lane * 4;
    float4 u0 = *(const float4*)&g_U[(size_t)b * OUT_DIM + c];
    float4 u1 = *(const float4*)&g_U[(size_t)(B_ROWS + b) * OUT_DIM + c];
    float4 o;
    o.x = gg0 * u0.x + gg1 * u1.x;
    o.y = gg0 * u0.y + gg1 * u1.y;
    o.z = gg0 * u0.z + gg1 * u1.z;
    o.w = gg0 * u0.w + gg1 * u1.w;
    *(float4*)&out[(size_t)b * OUT_DIM + c] = o;
}

// ---------------- kernel 5: pairwise Gram + kernel-sum + final scalar ------------
__global__ __launch_bounds__(256, 2) void k_pair_tc(float* __restrict__ out, int idx) {
    extern __shared__ char dyn[];
    __shared__ float sSqI[128], sSqJ[128], sRed[8];
    uint32_t sdyn = smem_u32(dyn);
    const int tid = threadIdx.x, lane = tid & 31, wid = tid >> 5;
    const int wm = wid & 3, wn = wid >> 2;

    int t = blockIdx.x;
    int s = 2079 - t;
    int a = (int)((sqrtf(8.f * (float)s + 1.f) - 1.f) * 0.5f);
    while ((a + 1) * (a + 2) / 2 <= s) a++;
    while (a * (a + 1) / 2 > s) a--;
    const int bi = 63 - a;
    const int bj = 63 - (s - a * (a + 1) / 2);
    const int i0 = bi * 128, j0 = bj * 128;

    if (tid < 128) { sSqI[tid] = g_sq[i0 + tid]; sSqJ[tid] = g_sq[j0 + tid]; }

    float acc[2][8][4];
#pragma unroll
    for (int aa = 0; aa < 2; aa++)
#pragma unroll
        for (int b = 0; b < 8; b++)
#pragma unroll
            for (int r = 0; r < 4; r++) acc[aa][b][r] = 0.f;

    const __half* A = g_Uh + (size_t)i0 * OUT_DIM;
    const __half* B = g_Uh + (size_t)j0 * OUT_DIM;

    load_chunk2(sdyn, A, B, 0, tid);
    CP_COMMIT();
#pragma unroll
    for (int p = 0; p < 4; p++) {
        if (p + 1 < 4) {
            load_chunk2(sdyn + ((p + 1) & 1) * SETSZ2, A, B, (p + 1) * 64, tid);
            CP_COMMIT();
            CP_WAIT(1);
        } else {
            CP_WAIT(0);
        }
        __syncthreads();
        compute_chunk2(sdyn + (p & 1) * SETSZ2, wm, wn, lane, acc);
        __syncthreads();
    }

    const float coef = g_coef;
    const float sgn = ((bi < 32) == (bj < 32)) ? 1.f : -1.f;
    float local = 0.f;
    float blockScale;

    if (bi != bj) {
        const int ibase = wm * 32 + (lane >> 2);
        const int jb0   = wn * 64 + (lane & 3) * 2;
#pragma unroll
        for (int mt = 0; mt < 2; mt++) {
            const float si0 = sSqI[ibase + mt * 16];
            const float si1 = sSqI[ibase + mt * 16 + 8];
#pragma unroll
            for (int n8 = 0; n8 < 8; n8++) {
                const float2 sj = *(const float2*)&sSqJ[jb0 + n8 * 8];
                const float* q = acc[mt][n8];
                local += kernF(si0 + sj.x - 2.f * q[0], coef);
                local += kernF(si0 + sj.y - 2.f * q[1], coef);
                local += kernF(si1 + sj.x - 2.f * q[2], coef);
                local += kernF(si1 + sj.y - 2.f * q[3], coef);
            }
        }
        blockScale = 2.f * sgn;
    } else {
#pragma unroll
        for (int mt = 0; mt < 2; mt++) {
            const int ibase = wm * 32 + mt * 16 + (lane >> 2);
#pragma unroll
            for (int n8 = 0; n8 < 8; n8++) {
                const int jbase = wn * 64 + n8 * 8 + (lane & 3) * 2;
#pragma unroll
                for (int r = 0; r < 4; r++) {
                    const int i = ibase + (r >> 1) * 8;
                    const int j = jbase + (r & 1);
                    float w = (j > i) ? 2.f : (j == i ? 1.f : 0.f);
                    local += w * kernF(sSqI[i] + sSqJ[j] - 2.f * acc[mt][n8][r], coef);
                }
            }
        }
        blockScale = sgn;
    }

#pragma unroll
    for (int off = 16; off; off >>= 1) local += __shfl_down_sync(0xffffffffu, local, off);
    if (lane == 0) sRed[wid] = local;
    __syncthreads();
    if (tid == 0) {
        float tot = 0.f;
#pragma unroll
        for (int ww = 0; ww < 8; ww++) tot += sRed[ww];
        atomicAdd(&g_loss, (double)tot * (double)blockScale);
        __threadfence();
        if (atomicAdd(&g_cnt2, 1u) == 2079u)
            out[idx] = (float)(-g_loss / ((double)B_ROWS * (double)B_ROWS));
    }
}

// ---------------- launch ----------------
extern "C" void kernel_launch(void* const* d_in, const int* in_sizes, int n_in,
                              void* d_out, int out_size) {
    const float* x    = (const float*)d_in[0];
    const float* Waux = (const float*)d_in[1];
    const float* baux = (const float*)d_in[2];
    const float* W    = (const float*)d_in[3];
    const float* bias = (const float*)d_in[4];
    float* out = (float*)d_out;

    cudaFuncSetAttribute(k_outs_tc, cudaFuncAttributeMaxDynamicSharedMemorySize, DYNSZ3);
    cudaFuncSetAttribute(k_pair_tc, cudaFuncAttributeMaxDynamicSharedMemorySize, DYNSZ2);

    k_prep<<<2305, 256>>>(x, W, Waux);
    k_outs_tc<<<dim3(4, 32), 256, DYNSZ3>>>(bias);
    k_rowstats<<<256, 256>>>();
    k_gates<<<1024, 256>>>(baux, out);
    k_pair_tc<<<2080, 256, DYNSZ2>>>(out, out_size - 1);
}